// round 10
// baseline (speedup 1.0000x reference)
#include <cuda_runtime.h>
#include <cstdint>

#define NN 100000
#define EE 1600000

// ---- device scratch ----
__device__ int   g_cnt[NN];       // zero-init by CUDA; re-zeroed each call in scan_local
__device__ int   g_off[NN + 1];
__device__ int   g_cur[NN];
__device__ int   g_bsum[1024];
__device__ int   g_csr[EE];
__device__ float g_dinv[NN];
__device__ float g_G[NN * 128];
__device__ float g_X2[NN * 128];

// ------------------------------------------------------------------
// CSR build
// ------------------------------------------------------------------
__global__ void count_kernel(const int* __restrict__ dst, int e) {
    int i = blockIdx.x * blockDim.x + threadIdx.x;
    if (i < e) atomicAdd(&g_cnt[dst[i]], 1);
}
// local exclusive scan (1024/block) + dinv + re-zero counts
__global__ __launch_bounds__(256) void scan_local_kernel(int n) {
    __shared__ int ssum[256];
    int t = threadIdx.x;
    int base = blockIdx.x * 1024 + t * 4;
    int c0 = (base + 0 < n) ? g_cnt[base + 0] : 0;
    int c1 = (base + 1 < n) ? g_cnt[base + 1] : 0;
    int c2 = (base + 2 < n) ? g_cnt[base + 2] : 0;
    int c3 = (base + 3 < n) ? g_cnt[base + 3] : 0;
    // dinv + reset for next graph replay
    if (base + 0 < n) { g_dinv[base + 0] = rsqrtf((float)c0 + 1.0f); g_cnt[base + 0] = 0; }
    if (base + 1 < n) { g_dinv[base + 1] = rsqrtf((float)c1 + 1.0f); g_cnt[base + 1] = 0; }
    if (base + 2 < n) { g_dinv[base + 2] = rsqrtf((float)c2 + 1.0f); g_cnt[base + 2] = 0; }
    if (base + 3 < n) { g_dinv[base + 3] = rsqrtf((float)c3 + 1.0f); g_cnt[base + 3] = 0; }
    int tsum = c0 + c1 + c2 + c3;
    ssum[t] = tsum;
    __syncthreads();
    for (int off = 1; off < 256; off <<= 1) {
        int v = (t >= off) ? ssum[t - off] : 0;
        __syncthreads();
        ssum[t] += v;
        __syncthreads();
    }
    int excl = ssum[t] - tsum;
    if (base + 0 < n) g_off[base + 0] = excl;
    if (base + 1 < n) g_off[base + 1] = excl + c0;
    if (base + 2 < n) g_off[base + 2] = excl + c0 + c1;
    if (base + 3 < n) g_off[base + 3] = excl + c0 + c1 + c2;
    if (t == 255) g_bsum[blockIdx.x] = ssum[255];
}
__global__ __launch_bounds__(1024) void scan_bsums_kernel(int nb) {
    __shared__ int s[1024];
    int t = threadIdx.x;
    int v = (t < nb) ? g_bsum[t] : 0;
    s[t] = v;
    __syncthreads();
    for (int off = 1; off < 1024; off <<= 1) {
        int u = (t >= off) ? s[t - off] : 0;
        __syncthreads();
        s[t] += u;
        __syncthreads();
    }
    if (t < nb) g_bsum[t] = s[t] - v;
}
__global__ void scan_add_kernel(int n, int e) {
    int i = blockIdx.x * blockDim.x + threadIdx.x;
    if (i < n) {
        int v = g_off[i] + g_bsum[i >> 10];
        g_off[i] = v;
        g_cur[i] = v;
    }
    if (i == 0) g_off[n] = e;
}
__global__ void scatter_kernel(const int* __restrict__ src,
                               const int* __restrict__ dst, int e) {
    int i = blockIdx.x * blockDim.x + threadIdx.x;
    if (i < e) {
        int pos = atomicAdd(&g_cur[dst[i]], 1);
        g_csr[pos] = src[i];
    }
}

// ------------------------------------------------------------------
// tf32 mma.sync GEMM (sm_80-compatible PTX; runs on tensor pipe)
// k-columns within each 8-group stored permuted [0,4,1,5,2,6,3,7]
// so each thread's (t4, t4+4) fragment pair is one LDS.64.
// ------------------------------------------------------------------
__device__ __forceinline__ uint32_t cvt_tf32(float x) {
    uint32_t r;
    asm("cvt.rna.tf32.f32 %0, %1;" : "=r"(r) : "f"(x));
    return r;
}
__device__ __forceinline__ void mma8(float* d, const uint32_t* a, const uint32_t* b) {
    asm volatile(
        "mma.sync.aligned.m16n8k8.row.col.f32.tf32.tf32.f32 "
        "{%0,%1,%2,%3}, {%4,%5,%6,%7}, {%8,%9}, {%0,%1,%2,%3};"
        : "+f"(d[0]), "+f"(d[1]), "+f"(d[2]), "+f"(d[3])
        : "r"(a[0]), "r"(a[1]), "r"(a[2]), "r"(a[3]), "r"(b[0]), "r"(b[1]));
}

// smem (floats): Bhi[128*132], Blo[128*132], Ahi[128*68], Alo[128*68]
#define OFF_BHI 0
#define OFF_BLO 16896
#define OFF_AHI 33792
#define OFF_ALO 42496
#define GEMM_SMEM_FL 51200
#define GEMM_SMEM_B (GEMM_SMEM_FL * 4)

// load one A chunk (K=64 cols starting at c*64) into 8 float4 regs
__device__ __forceinline__ void load_A_regs(
    const float* __restrict__ X, int trow, int c, int n, int tid, float4* va)
{
#pragma unroll
    for (int j = 0; j < 8; j++) {
        int i4 = tid + j * 256;
        int m = i4 >> 4, q = i4 & 15;
        int row = trow + m;
        va[j] = make_float4(0.f, 0.f, 0.f, 0.f);
        if (row < n)
            va[j] = *(const float4*)(X + (size_t)row * 128 + c * 64 + q * 4);
    }
}

// convert regs -> tf32 hi/lo, store to smem with permuted-k layout.
// cols q*4+e map to position (q>>1)*8 + (q&1) + 2*e within the 64-col chunk.
__device__ __forceinline__ void store_A_smem(float* sm, int tid, const float4* va)
{
#pragma unroll
    for (int j = 0; j < 8; j++) {
        int i4 = tid + j * 256;
        int m = i4 >> 4, q = i4 & 15;
        float4 v = va[j];
        uint32_t h0 = cvt_tf32(v.x), h1 = cvt_tf32(v.y);
        uint32_t h2 = cvt_tf32(v.z), h3 = cvt_tf32(v.w);
        uint32_t l0 = cvt_tf32(v.x - __uint_as_float(h0));
        uint32_t l1 = cvt_tf32(v.y - __uint_as_float(h1));
        uint32_t l2 = cvt_tf32(v.z - __uint_as_float(h2));
        uint32_t l3 = cvt_tf32(v.w - __uint_as_float(h3));
        int pos = (q >> 1) * 8 + (q & 1);
        float* ah = sm + OFF_AHI + m * 68 + pos;
        float* al = sm + OFF_ALO + m * 68 + pos;
        ah[0] = __uint_as_float(h0); ah[2] = __uint_as_float(h1);
        ah[4] = __uint_as_float(h2); ah[6] = __uint_as_float(h3);
        al[0] = __uint_as_float(l0); al[2] = __uint_as_float(l1);
        al[4] = __uint_as_float(l2); al[6] = __uint_as_float(l3);
    }
}

// G = (X @ W) * dinv[row]; persistent; M-tile 128, N=128, K=128 (2 chunks of 64)
__global__ __launch_bounds__(256) void gemm_mma_kernel(
    const float* __restrict__ Xext, const float* __restrict__ W,
    int n, int use_x2)
{
    extern __shared__ float sm[];
    const float* X = use_x2 ? g_X2 : Xext;
    int tid = threadIdx.x, w = tid >> 5, lane = tid & 31;
    int g = lane >> 2, t4 = lane & 3;

    // fill W hi/lo once: Bs[n][kperm] = W[k][n], stride 132, permuted k
    for (int i = tid; i < 128 * 128; i += 256) {
        int k = i >> 7, nn2 = i & 127;
        float wv = W[i];
        uint32_t hi = cvt_tf32(wv);
        uint32_t lo = cvt_tf32(wv - __uint_as_float(hi));
        int k8 = k & 7;
        int kperm = (k & ~7) | ((k8 < 4) ? (2 * k8) : (2 * (k8 - 4) + 1));
        sm[OFF_BHI + nn2 * 132 + kperm] = __uint_as_float(hi);
        sm[OFF_BLO + nn2 * 132 + kperm] = __uint_as_float(lo);
    }

    int rb = (w >> 1) * 32;       // warp row base (0,32,64,96)
    int cb = (w & 1) * 64;        // warp col base (0,64)
    int ntiles = (n + 127) >> 7;
    int stride = gridDim.x;

    float4 va[8];
    int t = blockIdx.x;
    if (t < ntiles) load_A_regs(X, t << 7, 0, n, tid, va);
    __syncthreads();   // W fill complete

    for (; t < ntiles; t += stride) {
        int trow = t << 7;

        float acc[2][8][4];
#pragma unroll
        for (int mi = 0; mi < 2; mi++)
#pragma unroll
            for (int ni = 0; ni < 8; ni++)
#pragma unroll
                for (int j = 0; j < 4; j++) acc[mi][ni][j] = 0.0f;

#pragma unroll
        for (int c = 0; c < 2; c++) {
            store_A_smem(sm, tid, va);
            __syncthreads();

            // prefetch next chunk
            int tn = (c == 0) ? t : t + stride;
            int cn = c ^ 1;
            if (tn < ntiles) load_A_regs(X, tn << 7, cn, n, tid, va);

            // compute chunk c
#pragma unroll 4
            for (int kb = 0; kb < 8; kb++) {
                int ka = kb * 8 + 2 * t4;           // permuted A col offset
                int kB = c * 64 + kb * 8 + 2 * t4;  // permuted B col offset
                uint32_t ah[2][4], al[2][4];
#pragma unroll
                for (int mi = 0; mi < 2; mi++) {
                    int r0 = rb + mi * 16 + g;
                    const float2* ph0 = (const float2*)(sm + OFF_AHI + r0 * 68 + ka);
                    const float2* ph1 = (const float2*)(sm + OFF_AHI + (r0 + 8) * 68 + ka);
                    float2 h0 = *ph0, h1 = *ph1;
                    ah[mi][0] = __float_as_uint(h0.x);
                    ah[mi][1] = __float_as_uint(h1.x);
                    ah[mi][2] = __float_as_uint(h0.y);
                    ah[mi][3] = __float_as_uint(h1.y);
                    const float2* pl0 = (const float2*)(sm + OFF_ALO + r0 * 68 + ka);
                    const float2* pl1 = (const float2*)(sm + OFF_ALO + (r0 + 8) * 68 + ka);
                    float2 l0 = *pl0, l1 = *pl1;
                    al[mi][0] = __float_as_uint(l0.x);
                    al[mi][1] = __float_as_uint(l1.x);
                    al[mi][2] = __float_as_uint(l0.y);
                    al[mi][3] = __float_as_uint(l1.y);
                }
#pragma unroll
                for (int ni = 0; ni < 8; ni++) {
                    int nidx = cb + ni * 8 + g;
                    float2 bhv = *(const float2*)(sm + OFF_BHI + nidx * 132 + kB);
                    float2 blv = *(const float2*)(sm + OFF_BLO + nidx * 132 + kB);
                    uint32_t bh[2] = {__float_as_uint(bhv.x), __float_as_uint(bhv.y)};
                    uint32_t bl[2] = {__float_as_uint(blv.x), __float_as_uint(blv.y)};
#pragma unroll
                    for (int mi = 0; mi < 2; mi++) {
                        mma8(acc[mi][ni], ah[mi], bh);
                        mma8(acc[mi][ni], ah[mi], bl);
                        mma8(acc[mi][ni], al[mi], bh);
                    }
                }
            }
            __syncthreads();
        }

        // epilogue: acc * dinv -> g_G
#pragma unroll
        for (int mi = 0; mi < 2; mi++) {
            int r0 = trow + rb + mi * 16 + g;
            int r1 = r0 + 8;
            float dv0 = (r0 < n) ? g_dinv[r0] : 0.f;
            float dv1 = (r1 < n) ? g_dinv[r1] : 0.f;
#pragma unroll
            for (int ni = 0; ni < 8; ni++) {
                int col = cb + ni * 8 + t4 * 2;
                if (r0 < n) {
                    float2 o = make_float2(acc[mi][ni][0] * dv0,
                                           acc[mi][ni][1] * dv0);
                    *(float2*)(g_G + (size_t)r0 * 128 + col) = o;
                }
                if (r1 < n) {
                    float2 o = make_float2(acc[mi][ni][2] * dv1,
                                           acc[mi][ni][3] * dv1);
                    *(float2*)(g_G + (size_t)r1 * 128 + col) = o;
                }
            }
        }
    }
}

// ------------------------------------------------------------------
// Fused CSR gather-reduce + finalize
// ------------------------------------------------------------------
__global__ __launch_bounds__(256) void agg_fin_kernel(
    const float* __restrict__ b, int n)
{
    int gid = blockIdx.x * blockDim.x + threadIdx.x;
    int node = gid >> 5;
    int lane = gid & 31;
    if (node >= n) return;

    int beg = g_off[node];
    int end = g_off[node + 1];
    size_t loff = (size_t)lane * 4;

    float4 acc = *(const float4*)(g_G + (size_t)node * 128 + loff);

    int j = beg;
    for (; j + 4 <= end; j += 4) {
        int s0 = g_csr[j + 0];
        int s1 = g_csr[j + 1];
        int s2 = g_csr[j + 2];
        int s3 = g_csr[j + 3];
        float4 v0 = *(const float4*)(g_G + (size_t)s0 * 128 + loff);
        float4 v1 = *(const float4*)(g_G + (size_t)s1 * 128 + loff);
        float4 v2 = *(const float4*)(g_G + (size_t)s2 * 128 + loff);
        float4 v3 = *(const float4*)(g_G + (size_t)s3 * 128 + loff);
        acc.x += v0.x + v1.x + v2.x + v3.x;
        acc.y += v0.y + v1.y + v2.y + v3.y;
        acc.z += v0.z + v1.z + v2.z + v3.z;
        acc.w += v0.w + v1.w + v2.w + v3.w;
    }
    for (; j < end; j++) {
        int s = g_csr[j];
        float4 v = *(const float4*)(g_G + (size_t)s * 128 + loff);
        acc.x += v.x; acc.y += v.y; acc.z += v.z; acc.w += v.w;
    }

    float dv = g_dinv[node];
    float4 bb = *(const float4*)(b + lane * 4);
    float4 o;
    o.x = fmaxf(fmaf(dv, acc.x, bb.x), 0.0f);
    o.y = fmaxf(fmaf(dv, acc.y, bb.y), 0.0f);
    o.z = fmaxf(fmaf(dv, acc.z, bb.z), 0.0f);
    o.w = fmaxf(fmaf(dv, acc.w, bb.w), 0.0f);
    *(float4*)(g_X2 + (size_t)node * 128 + loff) = o;
}

// ------------------------------------------------------------------
// Output GEMM: out = X2 @ Wout + bout   (K=128, N=40)
// ------------------------------------------------------------------
__global__ __launch_bounds__(320) void out_gemm_kernel(
    const float* __restrict__ Wout, const float* __restrict__ bout,
    float* __restrict__ out, int n)
{
    __shared__ float Ws[128 * 40];
    __shared__ float Xs[32][132];
    __shared__ float bs[40];

    int tid = threadIdx.x;
    int row0 = blockIdx.x * 32;

    for (int idx = tid; idx < 128 * 40; idx += 320) Ws[idx] = Wout[idx];
    if (tid < 40) bs[tid] = bout[tid];
    for (int idx = tid; idx < 32 * 32; idx += 320) {
        int r = idx >> 5, k4 = idx & 31;
        int gr = row0 + r;
        float4 v = (gr < n) ? *(const float4*)(g_X2 + (size_t)gr * 128 + k4 * 4)
                            : make_float4(0.f, 0.f, 0.f, 0.f);
        *(float4*)(&Xs[r][k4 * 4]) = v;
    }
    __syncthreads();

    int col = tid % 40;
    int ty = tid / 40;
    float acc[4] = {0.f, 0.f, 0.f, 0.f};
#pragma unroll 4
    for (int k = 0; k < 128; k++) {
        float w = Ws[k * 40 + col];
#pragma unroll
        for (int r = 0; r < 4; r++)
            acc[r] = fmaf(Xs[ty + 8 * r][k], w, acc[r]);
    }
#pragma unroll
    for (int r = 0; r < 4; r++) {
        int row = row0 + ty + 8 * r;
        if (row < n) out[(size_t)row * 40 + col] = acc[r] + bs[col];
    }
}

// ------------------------------------------------------------------
// launch
// ------------------------------------------------------------------
extern "C" void kernel_launch(void* const* d_in, const int* in_sizes, int n_in,
                              void* d_out, int out_size)
{
    const float* x    = (const float*)d_in[0];
    const int*   ei   = (const int*)d_in[1];
    const float* W1   = (const float*)d_in[2];
    const float* b1   = (const float*)d_in[3];
    const float* W2   = (const float*)d_in[4];
    const float* b2   = (const float*)d_in[5];
    const float* Wout = (const float*)d_in[6];
    const float* bout = (const float*)d_in[7];
    float* out = (float*)d_out;

    int n = in_sizes[0] / 128;
    int e = in_sizes[1] / 2;
    const int* src = ei;
    const int* dst = ei + e;

    cudaFuncSetAttribute(gemm_mma_kernel,
                         cudaFuncAttributeMaxDynamicSharedMemorySize, GEMM_SMEM_B);

    int nb_n = (n + 255) / 256;
    int nb_e = (e + 255) / 256;
    int nb_scan = (n + 1023) / 1024;
    long long agg_threads = (long long)n * 32;
    int nb_agg = (int)((agg_threads + 255) / 256);
    int nb_out = (n + 31) / 32;

    // CSR build (g_cnt is zeroed on module load and re-zeroed by scan_local)
    count_kernel<<<nb_e, 256>>>(dst, e);
    scan_local_kernel<<<nb_scan, 256>>>(n);
    scan_bsums_kernel<<<1, 1024>>>(nb_scan);
    scan_add_kernel<<<nb_n, 256>>>(n, e);
    scatter_kernel<<<nb_e, 256>>>(src, dst, e);

    // layer 1
    gemm_mma_kernel<<<152, 256, GEMM_SMEM_B>>>(x, W1, n, 0);
    agg_fin_kernel<<<nb_agg, 256>>>(b1, n);

    // layer 2
    gemm_mma_kernel<<<152, 256, GEMM_SMEM_B>>>(nullptr, W2, n, 1);
    agg_fin_kernel<<<nb_agg, 256>>>(b2, n);

    // output projection
    out_gemm_kernel<<<nb_out, 320>>>(Wout, bout, out, n);
}

// round 11
// speedup vs baseline: 1.0811x; 1.0811x over previous
#include <cuda_runtime.h>
#include <cstdint>

#define NN 100000
#define EE 1600000

// ---- device scratch ----
__device__ int   g_cnt[NN];       // zero-init by CUDA; re-zeroed each call in scan_local
__device__ int   g_off[NN + 1];
__device__ int   g_cur[NN];
__device__ int   g_bsum[1024];
__device__ int   g_csr[EE];
__device__ float g_dinv[NN];
__device__ float g_G[NN * 128];
__device__ float g_X2[NN * 128];

// ------------------------------------------------------------------
// CSR build
// ------------------------------------------------------------------
__global__ void count_kernel(const int* __restrict__ dst, int e) {
    int i = blockIdx.x * blockDim.x + threadIdx.x;
    if (i < e) atomicAdd(&g_cnt[dst[i]], 1);
}
// local exclusive scan (1024/block) + dinv + re-zero counts
__global__ __launch_bounds__(256) void scan_local_kernel(int n) {
    __shared__ int ssum[256];
    int t = threadIdx.x;
    int base = blockIdx.x * 1024 + t * 4;
    int c0 = (base + 0 < n) ? g_cnt[base + 0] : 0;
    int c1 = (base + 1 < n) ? g_cnt[base + 1] : 0;
    int c2 = (base + 2 < n) ? g_cnt[base + 2] : 0;
    int c3 = (base + 3 < n) ? g_cnt[base + 3] : 0;
    if (base + 0 < n) { g_dinv[base + 0] = rsqrtf((float)c0 + 1.0f); g_cnt[base + 0] = 0; }
    if (base + 1 < n) { g_dinv[base + 1] = rsqrtf((float)c1 + 1.0f); g_cnt[base + 1] = 0; }
    if (base + 2 < n) { g_dinv[base + 2] = rsqrtf((float)c2 + 1.0f); g_cnt[base + 2] = 0; }
    if (base + 3 < n) { g_dinv[base + 3] = rsqrtf((float)c3 + 1.0f); g_cnt[base + 3] = 0; }
    int tsum = c0 + c1 + c2 + c3;
    ssum[t] = tsum;
    __syncthreads();
    for (int off = 1; off < 256; off <<= 1) {
        int v = (t >= off) ? ssum[t - off] : 0;
        __syncthreads();
        ssum[t] += v;
        __syncthreads();
    }
    int excl = ssum[t] - tsum;
    if (base + 0 < n) g_off[base + 0] = excl;
    if (base + 1 < n) g_off[base + 1] = excl + c0;
    if (base + 2 < n) g_off[base + 2] = excl + c0 + c1;
    if (base + 3 < n) g_off[base + 3] = excl + c0 + c1 + c2;
    if (t == 255) g_bsum[blockIdx.x] = ssum[255];
}
__global__ __launch_bounds__(1024) void scan_bsums_kernel(int nb) {
    __shared__ int s[1024];
    int t = threadIdx.x;
    int v = (t < nb) ? g_bsum[t] : 0;
    s[t] = v;
    __syncthreads();
    for (int off = 1; off < 1024; off <<= 1) {
        int u = (t >= off) ? s[t - off] : 0;
        __syncthreads();
        s[t] += u;
        __syncthreads();
    }
    if (t < nb) g_bsum[t] = s[t] - v;
}
__global__ void scan_add_kernel(int n, int e) {
    int i = blockIdx.x * blockDim.x + threadIdx.x;
    if (i < n) {
        int v = g_off[i] + g_bsum[i >> 10];
        g_off[i] = v;
        g_cur[i] = v;
    }
    if (i == 0) g_off[n] = e;
}
__global__ void scatter_kernel(const int* __restrict__ src,
                               const int* __restrict__ dst, int e) {
    int i = blockIdx.x * blockDim.x + threadIdx.x;
    if (i < e) {
        int pos = atomicAdd(&g_cur[dst[i]], 1);
        g_csr[pos] = src[i];
    }
}

// ------------------------------------------------------------------
// tf32 mma.sync GEMM (sm_80-compatible PTX; runs on tensor pipe)
// R9-proven mainloop: scalar LDS fragments, natural k order.
// ------------------------------------------------------------------
__device__ __forceinline__ uint32_t cvt_tf32(float x) {
    uint32_t r;
    asm("cvt.rna.tf32.f32 %0, %1;" : "=r"(r) : "f"(x));
    return r;
}
__device__ __forceinline__ void mma8(float* d, const uint32_t* a, const uint32_t* b) {
    asm volatile(
        "mma.sync.aligned.m16n8k8.row.col.f32.tf32.tf32.f32 "
        "{%0,%1,%2,%3}, {%4,%5,%6,%7}, {%8,%9}, {%0,%1,%2,%3};"
        : "+f"(d[0]), "+f"(d[1]), "+f"(d[2]), "+f"(d[3])
        : "r"(a[0]), "r"(a[1]), "r"(a[2]), "r"(a[3]), "r"(b[0]), "r"(b[1]));
}

// smem (floats): Bhi[128*132], Blo[128*132], Ahi[128*68], Alo[128*68]
#define OFF_BHI 0
#define OFF_BLO 16896
#define OFF_AHI 33792
#define OFF_ALO 42496
#define GEMM_SMEM_FL 51200
#define GEMM_SMEM_B (GEMM_SMEM_FL * 4)

// load one A chunk (K=64 cols starting at c*64) into 8 float4 regs
__device__ __forceinline__ void load_A_regs(
    const float* __restrict__ X, int trow, int c, int n, int tid, float4* va)
{
#pragma unroll
    for (int j = 0; j < 8; j++) {
        int i4 = tid + j * 256;
        int m = i4 >> 4, q = i4 & 15;
        int row = trow + m;
        va[j] = make_float4(0.f, 0.f, 0.f, 0.f);
        if (row < n)
            va[j] = *(const float4*)(X + (size_t)row * 128 + c * 64 + q * 4);
    }
}

// convert regs -> tf32 hi/lo and store to smem A buffers (stride 68)
__device__ __forceinline__ void store_A_smem(float* sm, int tid, const float4* va)
{
#pragma unroll
    for (int j = 0; j < 8; j++) {
        int i4 = tid + j * 256;
        int m = i4 >> 4, q = i4 & 15;
        float4 v = va[j];
        uint32_t h0 = cvt_tf32(v.x), h1 = cvt_tf32(v.y);
        uint32_t h2 = cvt_tf32(v.z), h3 = cvt_tf32(v.w);
        uint32_t l0 = cvt_tf32(v.x - __uint_as_float(h0));
        uint32_t l1 = cvt_tf32(v.y - __uint_as_float(h1));
        uint32_t l2 = cvt_tf32(v.z - __uint_as_float(h2));
        uint32_t l3 = cvt_tf32(v.w - __uint_as_float(h3));
        float* ah = sm + OFF_AHI + m * 68 + q * 4;
        float* al = sm + OFF_ALO + m * 68 + q * 4;
        ah[0] = __uint_as_float(h0); ah[1] = __uint_as_float(h1);
        ah[2] = __uint_as_float(h2); ah[3] = __uint_as_float(h3);
        al[0] = __uint_as_float(l0); al[1] = __uint_as_float(l1);
        al[2] = __uint_as_float(l2); al[3] = __uint_as_float(l3);
    }
}

// G = (X @ W) * dinv[row]; persistent; M-tile 128, N=128, K=128 (2 chunks of 64)
__global__ __launch_bounds__(256) void gemm_mma_kernel(
    const float* __restrict__ Xext, const float* __restrict__ W,
    int n, int use_x2)
{
    extern __shared__ float sm[];
    const float* X = use_x2 ? g_X2 : Xext;
    int tid = threadIdx.x, w = tid >> 5, lane = tid & 31;
    int g = lane >> 2, t4 = lane & 3;

    // fill W hi/lo once: Bs[n][k] = W[k][n], stride 132
    for (int i = tid; i < 128 * 128; i += 256) {
        int k = i >> 7, nn2 = i & 127;
        float wv = W[i];
        uint32_t hi = cvt_tf32(wv);
        uint32_t lo = cvt_tf32(wv - __uint_as_float(hi));
        sm[OFF_BHI + nn2 * 132 + k] = __uint_as_float(hi);
        sm[OFF_BLO + nn2 * 132 + k] = __uint_as_float(lo);
    }

    int rb = (w >> 1) * 32;       // warp row base (0,32,64,96)
    int cb = (w & 1) * 64;        // warp col base (0,64)
    int ntiles = (n + 127) >> 7;
    int stride = gridDim.x;

    float4 va[8];
    int t = blockIdx.x;
    if (t < ntiles) load_A_regs(X, t << 7, 0, n, tid, va);
    __syncthreads();   // W fill complete (covers first store too)

    for (; t < ntiles; t += stride) {
        int trow = t << 7;

        float acc[2][8][4];
#pragma unroll
        for (int mi = 0; mi < 2; mi++)
#pragma unroll
            for (int ni = 0; ni < 8; ni++)
#pragma unroll
                for (int j = 0; j < 4; j++) acc[mi][ni][j] = 0.0f;

#pragma unroll
        for (int c = 0; c < 2; c++) {
            // store prefetched A chunk into smem (convert to tf32 hi/lo)
            store_A_smem(sm, tid, va);
            __syncthreads();

            // prefetch next chunk (this tile's chunk 1, or next tile's chunk 0)
            int tn = (c == 0) ? t : t + stride;
            int cn = c ^ 1;
            if (tn < ntiles) load_A_regs(X, tn << 7, cn, n, tid, va);

            // compute chunk c
#pragma unroll 2
            for (int kb = 0; kb < 8; kb++) {
                int kk = kb * 8 + t4;          // chunk-local A col
                int kB = c * 64 + kb * 8 + t4; // absolute B col
                uint32_t ah[2][4], al[2][4];
#pragma unroll
                for (int mi = 0; mi < 2; mi++) {
                    int r0 = rb + mi * 16 + g;
                    const float* basep = sm + OFF_AHI + r0 * 68 + kk;
                    ah[mi][0] = __float_as_uint(basep[0]);
                    ah[mi][1] = __float_as_uint(basep[8 * 68]);
                    ah[mi][2] = __float_as_uint(basep[4]);
                    ah[mi][3] = __float_as_uint(basep[8 * 68 + 4]);
                    const float* basel = sm + OFF_ALO + r0 * 68 + kk;
                    al[mi][0] = __float_as_uint(basel[0]);
                    al[mi][1] = __float_as_uint(basel[8 * 68]);
                    al[mi][2] = __float_as_uint(basel[4]);
                    al[mi][3] = __float_as_uint(basel[8 * 68 + 4]);
                }
#pragma unroll
                for (int ni = 0; ni < 8; ni++) {
                    int nidx = cb + ni * 8 + g;
                    uint32_t bh[2], bl[2];
                    const float* bph = sm + OFF_BHI + nidx * 132 + kB;
                    const float* bpl = sm + OFF_BLO + nidx * 132 + kB;
                    bh[0] = __float_as_uint(bph[0]);
                    bh[1] = __float_as_uint(bph[4]);
                    bl[0] = __float_as_uint(bpl[0]);
                    bl[1] = __float_as_uint(bpl[4]);
#pragma unroll
                    for (int mi = 0; mi < 2; mi++) {
                        mma8(acc[mi][ni], ah[mi], bh);
                        mma8(acc[mi][ni], ah[mi], bl);
                        mma8(acc[mi][ni], al[mi], bh);
                    }
                }
            }
            __syncthreads();
        }

        // epilogue: acc * dinv -> g_G
#pragma unroll
        for (int mi = 0; mi < 2; mi++) {
            int r0 = trow + rb + mi * 16 + g;
            int r1 = r0 + 8;
            float dv0 = (r0 < n) ? g_dinv[r0] : 0.f;
            float dv1 = (r1 < n) ? g_dinv[r1] : 0.f;
#pragma unroll
            for (int ni = 0; ni < 8; ni++) {
                int col = cb + ni * 8 + t4 * 2;
                if (r0 < n) {
                    float2 o = make_float2(acc[mi][ni][0] * dv0,
                                           acc[mi][ni][1] * dv0);
                    *(float2*)(g_G + (size_t)r0 * 128 + col) = o;
                }
                if (r1 < n) {
                    float2 o = make_float2(acc[mi][ni][2] * dv1,
                                           acc[mi][ni][3] * dv1);
                    *(float2*)(g_G + (size_t)r1 * 128 + col) = o;
                }
            }
        }
    }
}

// ------------------------------------------------------------------
// Fused CSR gather-reduce + finalize
// ------------------------------------------------------------------
__global__ __launch_bounds__(256) void agg_fin_kernel(
    const float* __restrict__ b, int n)
{
    int gid = blockIdx.x * blockDim.x + threadIdx.x;
    int node = gid >> 5;
    int lane = gid & 31;
    if (node >= n) return;

    int beg = g_off[node];
    int end = g_off[node + 1];
    size_t loff = (size_t)lane * 4;

    float4 acc = *(const float4*)(g_G + (size_t)node * 128 + loff);

    int j = beg;
    for (; j + 4 <= end; j += 4) {
        int s0 = g_csr[j + 0];
        int s1 = g_csr[j + 1];
        int s2 = g_csr[j + 2];
        int s3 = g_csr[j + 3];
        float4 v0 = *(const float4*)(g_G + (size_t)s0 * 128 + loff);
        float4 v1 = *(const float4*)(g_G + (size_t)s1 * 128 + loff);
        float4 v2 = *(const float4*)(g_G + (size_t)s2 * 128 + loff);
        float4 v3 = *(const float4*)(g_G + (size_t)s3 * 128 + loff);
        acc.x += v0.x + v1.x + v2.x + v3.x;
        acc.y += v0.y + v1.y + v2.y + v3.y;
        acc.z += v0.z + v1.z + v2.z + v3.z;
        acc.w += v0.w + v1.w + v2.w + v3.w;
    }
    for (; j < end; j++) {
        int s = g_csr[j];
        float4 v = *(const float4*)(g_G + (size_t)s * 128 + loff);
        acc.x += v.x; acc.y += v.y; acc.z += v.z; acc.w += v.w;
    }

    float dv = g_dinv[node];
    float4 bb = *(const float4*)(b + lane * 4);
    float4 o;
    o.x = fmaxf(fmaf(dv, acc.x, bb.x), 0.0f);
    o.y = fmaxf(fmaf(dv, acc.y, bb.y), 0.0f);
    o.z = fmaxf(fmaf(dv, acc.z, bb.z), 0.0f);
    o.w = fmaxf(fmaf(dv, acc.w, bb.w), 0.0f);
    *(float4*)(g_X2 + (size_t)node * 128 + loff) = o;
}

// ------------------------------------------------------------------
// Output GEMM: out = X2 @ Wout + bout   (K=128, N=40)
// ------------------------------------------------------------------
__global__ __launch_bounds__(320) void out_gemm_kernel(
    const float* __restrict__ Wout, const float* __restrict__ bout,
    float* __restrict__ out, int n)
{
    __shared__ float Ws[128 * 40];
    __shared__ float Xs[32][132];
    __shared__ float bs[40];

    int tid = threadIdx.x;
    int row0 = blockIdx.x * 32;

    for (int idx = tid; idx < 128 * 40; idx += 320) Ws[idx] = Wout[idx];
    if (tid < 40) bs[tid] = bout[tid];
    for (int idx = tid; idx < 32 * 32; idx += 320) {
        int r = idx >> 5, k4 = idx & 31;
        int gr = row0 + r;
        float4 v = (gr < n) ? *(const float4*)(g_X2 + (size_t)gr * 128 + k4 * 4)
                            : make_float4(0.f, 0.f, 0.f, 0.f);
        *(float4*)(&Xs[r][k4 * 4]) = v;
    }
    __syncthreads();

    int col = tid % 40;
    int ty = tid / 40;
    float acc[4] = {0.f, 0.f, 0.f, 0.f};
#pragma unroll 4
    for (int k = 0; k < 128; k++) {
        float w = Ws[k * 40 + col];
#pragma unroll
        for (int r = 0; r < 4; r++)
            acc[r] = fmaf(Xs[ty + 8 * r][k], w, acc[r]);
    }
#pragma unroll
    for (int r = 0; r < 4; r++) {
        int row = row0 + ty + 8 * r;
        if (row < n) out[(size_t)row * 40 + col] = acc[r] + bs[col];
    }
}

// ------------------------------------------------------------------
// launch
// ------------------------------------------------------------------
extern "C" void kernel_launch(void* const* d_in, const int* in_sizes, int n_in,
                              void* d_out, int out_size)
{
    const float* x    = (const float*)d_in[0];
    const int*   ei   = (const int*)d_in[1];
    const float* W1   = (const float*)d_in[2];
    const float* b1   = (const float*)d_in[3];
    const float* W2   = (const float*)d_in[4];
    const float* b2   = (const float*)d_in[5];
    const float* Wout = (const float*)d_in[6];
    const float* bout = (const float*)d_in[7];
    float* out = (float*)d_out;

    int n = in_sizes[0] / 128;
    int e = in_sizes[1] / 2;
    const int* src = ei;
    const int* dst = ei + e;

    cudaFuncSetAttribute(gemm_mma_kernel,
                         cudaFuncAttributeMaxDynamicSharedMemorySize, GEMM_SMEM_B);

    int nb_n = (n + 255) / 256;
    int nb_e = (e + 255) / 256;
    int nb_scan = (n + 1023) / 1024;
    long long agg_threads = (long long)n * 32;
    int nb_agg = (int)((agg_threads + 255) / 256);
    int nb_out = (n + 31) / 32;

    // CSR build (g_cnt zeroed on load and re-zeroed by scan_local each call)
    count_kernel<<<nb_e, 256>>>(dst, e);
    scan_local_kernel<<<nb_scan, 256>>>(n);
    scan_bsums_kernel<<<1, 1024>>>(nb_scan);
    scan_add_kernel<<<nb_n, 256>>>(n, e);
    scatter_kernel<<<nb_e, 256>>>(src, dst, e);

    // layer 1
    gemm_mma_kernel<<<152, 256, GEMM_SMEM_B>>>(x, W1, n, 0);
    agg_fin_kernel<<<nb_agg, 256>>>(b1, n);

    // layer 2
    gemm_mma_kernel<<<152, 256, GEMM_SMEM_B>>>(nullptr, W2, n, 1);
    agg_fin_kernel<<<nb_agg, 256>>>(b2, n);

    // output projection
    out_gemm_kernel<<<nb_out, 320>>>(Wout, bout, out, n);
}